// round 14
// baseline (speedup 1.0000x reference)
#include <cuda_runtime.h>
#include <cuda_fp16.h>
#include <math.h>
#include <cstdint>

#define N_NODES 20000
#define N_EDGES 640000
#define D 256
#define N_RELS 8
#define N_BASES 4
#define KA 1280              // A & B K: [T_hi(1024)|x_hi(256)]  plain fp16

// ---------------- device scratch (allocation-free rule) ----------------
__device__ __align__(16) __half g_A3[(size_t)N_NODES * KA];    // 51MB fp16
__device__ __align__(16) __half g_B2[(size_t)256 * KA];        // 0.65MB [out-col n][k]
__device__ __align__(16) __half g_xh[(size_t)N_NODES * 256];   // 10MB fp16 mirror of x
__device__ int g_hist[N_NODES];
__device__ int g_cursor[N_NODES];
__device__ int g_start[N_NODES + 1];
__device__ uint32_t g_edges[N_EDGES];   // packed src | (type<<15)

__device__ __forceinline__ float gelu_exact(float x) {
    return 0.5f * x * (1.0f + erff(x * 0.70710678118654752440f));
}
__device__ __forceinline__ uint32_t smem_to_u32(const void* p) {
    uint32_t a;
    asm("{ .reg .u64 t; cvta.to.shared.u64 t, %1; cvt.u32.u64 %0, t; }" : "=r"(a) : "l"(p));
    return a;
}
__device__ __forceinline__ void cp_async16(uint32_t dst, const void* src, int src_sz) {
    asm volatile("cp.async.cg.shared.global [%0], [%1], 16, %2;" :: "r"(dst), "l"(src), "r"(src_sz) : "memory");
}
__device__ __forceinline__ void cp_async_commit() { asm volatile("cp.async.commit_group;" ::: "memory"); }
template <int N> __device__ __forceinline__ void cp_async_wait() {
    asm volatile("cp.async.wait_group %0;" :: "n"(N) : "memory");
}
__device__ __forceinline__ void ldsm_x4(uint32_t& r0, uint32_t& r1, uint32_t& r2, uint32_t& r3, uint32_t addr) {
    asm volatile("ldmatrix.sync.aligned.m8n8.x4.shared.b16 {%0,%1,%2,%3}, [%4];"
                 : "=r"(r0), "=r"(r1), "=r"(r2), "=r"(r3) : "r"(addr));
}
__device__ __forceinline__ void mma16816(float* d, uint32_t a0, uint32_t a1, uint32_t a2, uint32_t a3,
                                         uint32_t b0, uint32_t b1) {
    asm volatile("mma.sync.aligned.m16n8k16.row.col.f32.f16.f16.f32 "
                 "{%0,%1,%2,%3}, {%4,%5,%6,%7}, {%8,%9}, {%0,%1,%2,%3};"
                 : "+f"(d[0]), "+f"(d[1]), "+f"(d[2]), "+f"(d[3])
                 : "r"(a0), "r"(a1), "r"(a2), "r"(a3), "r"(b0), "r"(b1));
}

// ---------------------------------------------------------------------------
// Prep: convert x -> fp16 mirror (4 elems/thread) and zero g_hist
// ---------------------------------------------------------------------------
__global__ void __launch_bounds__(256) prep_x_kernel(const float* __restrict__ x) {
    int gid = blockIdx.x * blockDim.x + threadIdx.x;
    if (gid < N_NODES * 64) {
        float4 v = ((const float4*)x)[gid];
        __half2 a = __halves2half2(__float2half(v.x), __float2half(v.y));
        __half2 b = __halves2half2(__float2half(v.z), __float2half(v.w));
        ((__half2*)g_xh)[gid * 2 + 0] = a;
        ((__half2*)g_xh)[gid * 2 + 1] = b;
    }
    if (gid < N_NODES) g_hist[gid] = 0;
}

// 8 edges per thread (N_EDGES % 8 == 0)
__global__ void __launch_bounds__(256) hist_kernel(const int* __restrict__ dst) {
    int g8 = (blockIdx.x * blockDim.x + threadIdx.x) * 8;
    if (g8 >= N_EDGES) return;
    int4 d0 = *(const int4*)(dst + g8);
    int4 d1 = *(const int4*)(dst + g8 + 4);
    atomicAdd(&g_hist[d0.x], 1);
    atomicAdd(&g_hist[d0.y], 1);
    atomicAdd(&g_hist[d0.z], 1);
    atomicAdd(&g_hist[d0.w], 1);
    atomicAdd(&g_hist[d1.x], 1);
    atomicAdd(&g_hist[d1.y], 1);
    atomicAdd(&g_hist[d1.z], 1);
    atomicAdd(&g_hist[d1.w], 1);
}

// single block 1024 threads, 20 bins each
__global__ void __launch_bounds__(1024) scan_kernel() {
    __shared__ int sm[1024];
    int t = threadIdx.x;
    int base = t * 20;
    int cnt[20];
    int s = 0;
#pragma unroll
    for (int i = 0; i < 20; i++) {
        int idx = base + i;
        int c = (idx < N_NODES) ? g_hist[idx] : 0;
        cnt[i] = c; s += c;
    }
    sm[t] = s;
    __syncthreads();
    for (int off = 1; off < 1024; off <<= 1) {
        int v = (t >= off) ? sm[t - off] : 0;
        __syncthreads();
        sm[t] += v;
        __syncthreads();
    }
    int run = (t > 0) ? sm[t - 1] : 0;
#pragma unroll
    for (int i = 0; i < 20; i++) {
        int idx = base + i;
        if (idx < N_NODES) {
            g_start[idx] = run;
            g_cursor[idx] = run;
            run += cnt[i];
        }
    }
    if (t == 1023) g_start[N_NODES] = sm[1023];
}

// 8 edges per thread
__global__ void __launch_bounds__(256) reorder_kernel(const int* __restrict__ src,
                                                      const int* __restrict__ dst,
                                                      const int* __restrict__ et) {
    int g8 = (blockIdx.x * blockDim.x + threadIdx.x) * 8;
    if (g8 >= N_EDGES) return;
    int4 s0 = *(const int4*)(src + g8);
    int4 s1 = *(const int4*)(src + g8 + 4);
    int4 d0 = *(const int4*)(dst + g8);
    int4 d1 = *(const int4*)(dst + g8 + 4);
    int4 t0 = *(const int4*)(et + g8);
    int4 t1 = *(const int4*)(et + g8 + 4);
    int p0 = atomicAdd(&g_cursor[d0.x], 1);
    int p1 = atomicAdd(&g_cursor[d0.y], 1);
    int p2 = atomicAdd(&g_cursor[d0.z], 1);
    int p3 = atomicAdd(&g_cursor[d0.w], 1);
    int p4 = atomicAdd(&g_cursor[d1.x], 1);
    int p5 = atomicAdd(&g_cursor[d1.y], 1);
    int p6 = atomicAdd(&g_cursor[d1.z], 1);
    int p7 = atomicAdd(&g_cursor[d1.w], 1);
    g_edges[p0] = (uint32_t)s0.x | ((uint32_t)t0.x << 15);
    g_edges[p1] = (uint32_t)s0.y | ((uint32_t)t0.y << 15);
    g_edges[p2] = (uint32_t)s0.z | ((uint32_t)t0.z << 15);
    g_edges[p3] = (uint32_t)s0.w | ((uint32_t)t0.w << 15);
    g_edges[p4] = (uint32_t)s1.x | ((uint32_t)t1.x << 15);
    g_edges[p5] = (uint32_t)s1.y | ((uint32_t)t1.y << 15);
    g_edges[p6] = (uint32_t)s1.z | ((uint32_t)t1.z << 15);
    g_edges[p7] = (uint32_t)s1.w | ((uint32_t)t1.w << 15);
}

// ---------------------------------------------------------------------------
// Prep B2 (K = 1280 fp16):
//   k<1024  : b=k>>8, i=k&255 -> fp16(basis[b][i][n])
//   k>=1024 : i=k&255         -> fp16(loop_w[i][n])
// ---------------------------------------------------------------------------
__global__ void __launch_bounds__(256) prep_b2_kernel(const float* __restrict__ basis,
                                                      const float* __restrict__ loopw) {
    int n = blockIdx.x;   // 0..255
    for (int k = threadIdx.x; k < KA; k += 256) {
        float w;
        if (k < 1024) {
            int b = k >> 8, i = k & 255;
            w = basis[(size_t)b * 65536 + (size_t)i * 256 + n];
        } else {
            int i = k & 255;
            w = loopw[(size_t)i * 256 + n];
        }
        g_B2[(size_t)n * KA + k] = __float2half(w);
    }
}

// ---------------------------------------------------------------------------
// Fused gather(fp16) + aggregate + combine: one warp per node.
// A row layout (KA=1280): [T_hi(1024)|x_hi(256)]
// ---------------------------------------------------------------------------
__device__ __forceinline__ void round8_store(__half* rowbase, int off, const float* v) {
    union { __half2 h2[4]; uint4 u; } p;
#pragma unroll
    for (int q = 0; q < 4; q++)
        p.h2[q] = __halves2half2(__float2half(v[q * 2]), __float2half(v[q * 2 + 1]));
    *(uint4*)(rowbase + off) = p.u;
}

__global__ void __launch_bounds__(256) agg_kernel(const float* __restrict__ comp) {
    __shared__ float4 cs4[N_RELS];
    int tid = threadIdx.x;
    if (tid < N_RELS)
        cs4[tid] = make_float4(comp[tid * 4 + 0], comp[tid * 4 + 1], comp[tid * 4 + 2], comp[tid * 4 + 3]);
    __syncthreads();

    int v = blockIdx.x * 8 + (tid >> 5);
    int lane = tid & 31;
    if (v >= N_NODES) return;

    int s0 = g_start[v];
    int s1 = g_start[v + 1];
    int c0 = lane * 8;

    float accT[4][8];
#pragma unroll
    for (int b = 0; b < 4; b++)
#pragma unroll
        for (int j = 0; j < 8; j++) accT[b][j] = 0.f;

    auto accum = [&](uint32_t p, uint4 xv) {
        float4 cv = cs4[p >> 15];
        const __half2* h2 = (const __half2*)&xv;
        float2 f0 = __half22float2(h2[0]);
        float2 f1 = __half22float2(h2[1]);
        float2 f2 = __half22float2(h2[2]);
        float2 f3 = __half22float2(h2[3]);
        float c;
        c = cv.x;
        accT[0][0] += c * f0.x; accT[0][1] += c * f0.y; accT[0][2] += c * f1.x; accT[0][3] += c * f1.y;
        accT[0][4] += c * f2.x; accT[0][5] += c * f2.y; accT[0][6] += c * f3.x; accT[0][7] += c * f3.y;
        c = cv.y;
        accT[1][0] += c * f0.x; accT[1][1] += c * f0.y; accT[1][2] += c * f1.x; accT[1][3] += c * f1.y;
        accT[1][4] += c * f2.x; accT[1][5] += c * f2.y; accT[1][6] += c * f3.x; accT[1][7] += c * f3.y;
        c = cv.z;
        accT[2][0] += c * f0.x; accT[2][1] += c * f0.y; accT[2][2] += c * f1.x; accT[2][3] += c * f1.y;
        accT[2][4] += c * f2.x; accT[2][5] += c * f2.y; accT[2][6] += c * f3.x; accT[2][7] += c * f3.y;
        c = cv.w;
        accT[3][0] += c * f0.x; accT[3][1] += c * f0.y; accT[3][2] += c * f1.x; accT[3][3] += c * f1.y;
        accT[3][4] += c * f2.x; accT[3][5] += c * f2.y; accT[3][6] += c * f3.x; accT[3][7] += c * f3.y;
    };

    int e = s0;
    for (; e + 4 <= s1; e += 4) {
        uint32_t p[4];
        uint4 xv[4];
#pragma unroll
        for (int j = 0; j < 4; j++) p[j] = __ldg(&g_edges[e + j]);
#pragma unroll
        for (int j = 0; j < 4; j++)
            xv[j] = *(const uint4*)(g_xh + (size_t)(p[j] & 32767) * 256 + c0);
#pragma unroll
        for (int j = 0; j < 4; j++) accum(p[j], xv[j]);
    }
    for (; e < s1; e++) {
        uint32_t p = __ldg(&g_edges[e]);
        uint4 xv = *(const uint4*)(g_xh + (size_t)(p & 32767) * 256 + c0);
        accum(p, xv);
    }

    __half* arow = g_A3 + (size_t)v * KA;
#pragma unroll
    for (int b = 0; b < 4; b++)
        round8_store(arow, b * 256 + c0, accT[b]);
    // x part: copy the already-quantized fp16 row
    *(uint4*)(arow + 1024 + c0) = *(const uint4*)(g_xh + (size_t)v * 256 + c0);
}

// ---------------------------------------------------------------------------
// Fused GEMM + GELU + LayerNorm:
//   rgcn[32,256] = A[m0:m0+32, 1280] @ B2^T ; h = gelu(rgcn + bias + x);
//   out = LN(h)*gamma + beta  — all in one CTA per 32-row tile (625 tiles).
// Warp tile 32x32: 8 warps over N. K-chunk 32, double-buffered cp.async.
// ---------------------------------------------------------------------------
#define KCH 32
#define NCH (KA / KCH)          // 40
#define ROWB 80
#define A_TILE (32 * ROWB)      // 2560
#define B_TILE (256 * ROWB)     // 20480
#define MAINLOOP_SMEM (2 * A_TILE + 2 * B_TILE)   // 46080
#define SROW 260                // fp32 row pitch for epilogue buffer
#define EPI_SMEM (32 * SROW * 4)                  // 33280
#define GEMM_SMEM MAINLOOP_SMEM

__global__ void __launch_bounds__(256) gemm_fused_kernel(const float* __restrict__ x,
                                                         const float* __restrict__ bias,
                                                         const float* __restrict__ gamma,
                                                         const float* __restrict__ beta,
                                                         float* __restrict__ out) {
    extern __shared__ __align__(16) char dyn[];
    const uint32_t sAu[2] = { smem_to_u32(dyn), smem_to_u32(dyn + A_TILE) };
    const uint32_t sBu[2] = { smem_to_u32(dyn + 2 * A_TILE), smem_to_u32(dyn + 2 * A_TILE + B_TILE) };
    float* sC = (float*)dyn;   // epilogue overlay (after mainloop)

    const int tid = threadIdx.x;
    const int lane = tid & 31;
    const int wid = tid >> 5;          // warp_n = wid (0..7), 32 cols each
    const int m0 = blockIdx.x * 32;    // 625 * 32 = 20000 exactly

    // A loader: 32 rows x 4 x 16B = 128 chunks; threads 0..127
    const int ar = tid >> 2;
    const int ac = tid & 3;
    const __half* aBase = g_A3 + (size_t)(m0 + ar) * KA + ac * 8;
    const uint32_t aDst = ar * ROWB + ac * 16;
    const bool aActive = (tid < 128);

    auto load_chunk = [&](int c, int s) {
        int k0 = c * KCH;
        if (aActive) cp_async16(sAu[s] + aDst, aBase + k0, 16);
#pragma unroll
        for (int i = 0; i < 4; i++) {
            int cid = tid + i * 256;
            int br = cid >> 2, bc = cid & 3;
            cp_async16(sBu[s] + br * ROWB + bc * 16,
                       g_B2 + (size_t)br * KA + k0 + bc * 8, 16);
        }
        cp_async_commit();
    };

    float acc[2][4][4];
#pragma unroll
    for (int i = 0; i < 2; i++)
#pragma unroll
        for (int t = 0; t < 4; t++)
#pragma unroll
            for (int q = 0; q < 4; q++) acc[i][t][q] = 0.0f;

    const uint32_t aLd = (lane & 15) * ROWB + (lane >> 4) * 16;
    const uint32_t bLd = (wid * 32 + ((lane >> 4) << 3) + (lane & 7)) * ROWB + (((lane >> 3) & 1) << 4);

    load_chunk(0, 0);
    for (int c = 0; c < NCH; c++) {
        if (c + 1 < NCH) load_chunk(c + 1, (c + 1) & 1);
        if (c + 1 < NCH) cp_async_wait<1>(); else cp_async_wait<0>();
        __syncthreads();
        const int s = c & 1;
#pragma unroll
        for (int kk = 0; kk < 2; kk++) {
            uint32_t a[2][4];
#pragma unroll
            for (int i = 0; i < 2; i++)
                ldsm_x4(a[i][0], a[i][1], a[i][2], a[i][3],
                        sAu[s] + aLd + i * 16 * ROWB + kk * 32);
            uint32_t b[2][4];
#pragma unroll
            for (int j = 0; j < 2; j++)
                ldsm_x4(b[j][0], b[j][1], b[j][2], b[j][3],
                        sBu[s] + bLd + j * 16 * ROWB + kk * 32);
#pragma unroll
            for (int i = 0; i < 2; i++)
#pragma unroll
                for (int t = 0; t < 4; t++)
                    mma16816(acc[i][t], a[i][0], a[i][1], a[i][2], a[i][3],
                             b[t >> 1][(t & 1) * 2], b[t >> 1][(t & 1) * 2 + 1]);
        }
        __syncthreads();
    }

    // ---- epilogue phase 1: spill acc -> smem fp32 [32][SROW]
    const int colBase = wid * 32 + (lane & 3) * 2;
#pragma unroll
    for (int i = 0; i < 2; i++) {
        int r0 = i * 16 + (lane >> 2);
#pragma unroll
        for (int half = 0; half < 2; half++) {
            int r = r0 + half * 8;
#pragma unroll
            for (int t = 0; t < 4; t++)
                *(float2*)(sC + r * SROW + colBase + t * 8) =
                    make_float2(acc[i][t][half * 2], acc[i][t][half * 2 + 1]);
        }
    }
    __syncthreads();

    // ---- epilogue phase 2: warp w handles rows 4w..4w+3; GELU + LN
#pragma unroll
    for (int rr = 0; rr < 4; rr++) {
        int r = wid * 4 + rr;
        int m = m0 + r;
        int c0 = lane * 8;

        float h[8];
        {
            const float* srow = sC + r * SROW + c0;
            const float4* xr = (const float4*)(x + (size_t)m * 256 + c0);
            const float4* br = (const float4*)(bias + c0);
            float4 x0 = __ldg(xr), x1 = __ldg(xr + 1);
            float4 b0 = __ldg(br), b1 = __ldg(br + 1);
            h[0] = gelu_exact(srow[0] + b0.x + x0.x);
            h[1] = gelu_exact(srow[1] + b0.y + x0.y);
            h[2] = gelu_exact(srow[2] + b0.z + x0.z);
            h[3] = gelu_exact(srow[3] + b0.w + x0.w);
            h[4] = gelu_exact(srow[4] + b1.x + x1.x);
            h[5] = gelu_exact(srow[5] + b1.y + x1.y);
            h[6] = gelu_exact(srow[6] + b1.z + x1.z);
            h[7] = gelu_exact(srow[7] + b1.w + x1.w);
        }

        float s = 0.f;
#pragma unroll
        for (int i = 0; i < 8; i++) s += h[i];
#pragma unroll
        for (int off = 16; off > 0; off >>= 1) s += __shfl_xor_sync(0xffffffffu, s, off);
        float mu = s * (1.0f / 256.0f);

        float var = 0.f;
#pragma unroll
        for (int i = 0; i < 8; i++) {
            float dlt = h[i] - mu;
            var = fmaf(dlt, dlt, var);
        }
#pragma unroll
        for (int off = 16; off > 0; off >>= 1) var += __shfl_xor_sync(0xffffffffu, var, off);
        float inv = rsqrtf(var * (1.0f / 256.0f) + 1e-5f);

        float4 g0 = __ldg((const float4*)(gamma + c0));
        float4 g1 = __ldg((const float4*)(gamma + c0) + 1);
        float4 be0 = __ldg((const float4*)(beta + c0));
        float4 be1 = __ldg((const float4*)(beta + c0) + 1);

        float4 o0, o1;
        o0.x = (h[0] - mu) * inv * g0.x + be0.x;
        o0.y = (h[1] - mu) * inv * g0.y + be0.y;
        o0.z = (h[2] - mu) * inv * g0.z + be0.z;
        o0.w = (h[3] - mu) * inv * g0.w + be0.w;
        o1.x = (h[4] - mu) * inv * g1.x + be1.x;
        o1.y = (h[5] - mu) * inv * g1.y + be1.y;
        o1.z = (h[6] - mu) * inv * g1.z + be1.z;
        o1.w = (h[7] - mu) * inv * g1.w + be1.w;

        float4* orow = (float4*)(out + (size_t)m * 256 + c0);
        orow[0] = o0;
        orow[1] = o1;
    }
}

extern "C" void kernel_launch(void* const* d_in, const int* in_sizes, int n_in,
                              void* d_out, int out_size) {
    const float* x     = (const float*)d_in[0];
    const int*   src   = (const int*)  d_in[1];
    const int*   dst   = (const int*)  d_in[2];
    const int*   et    = (const int*)  d_in[3];
    const float* basis = (const float*)d_in[4];
    const float* comp  = (const float*)d_in[5];
    const float* loopw = (const float*)d_in[6];
    const float* bias  = (const float*)d_in[7];
    const float* gamma = (const float*)d_in[8];
    const float* beta  = (const float*)d_in[9];
    float* out = (float*)d_out;

    static bool attr_set = false;
    if (!attr_set) {
        cudaFuncSetAttribute(gemm_fused_kernel, cudaFuncAttributeMaxDynamicSharedMemorySize, GEMM_SMEM);
        attr_set = true;
    }

    prep_x_kernel<<<(N_NODES * 64 + 255) / 256, 256>>>(x);
    hist_kernel<<<(N_EDGES / 8 + 255) / 256, 256>>>(dst);
    scan_kernel<<<1, 1024>>>();
    reorder_kernel<<<(N_EDGES / 8 + 255) / 256, 256>>>(src, dst, et);
    prep_b2_kernel<<<256, 256>>>(basis, loopw);
    agg_kernel<<<(N_NODES + 7) / 8, 256>>>(comp);
    gemm_fused_kernel<<<N_NODES / 32, 256, GEMM_SMEM>>>(x, bias, gamma, beta, out);
}

// round 15
// speedup vs baseline: 1.0429x; 1.0429x over previous
#include <cuda_runtime.h>
#include <cuda_fp16.h>
#include <math.h>
#include <cstdint>

#define N_NODES 20000
#define N_EDGES 640000
#define D 256
#define N_RELS 8
#define N_BASES 4
#define KA 1280              // A & B K: [T_hi(1024)|x_hi(256)]  plain fp16

// ---------------- device scratch (allocation-free rule) ----------------
__device__ __align__(16) __half g_A3[(size_t)N_NODES * KA];    // 51MB fp16
__device__ __align__(16) __half g_B2[(size_t)256 * KA];        // 0.65MB [out-col n][k]
__device__ __align__(16) __half g_xh[(size_t)N_NODES * 256];   // 10MB fp16 mirror of x
__device__ int g_hist[N_NODES];
__device__ int g_cursor[N_NODES];
__device__ int g_start[N_NODES + 1];
__device__ uint32_t g_edges[N_EDGES];   // packed src | (type<<15)

__device__ __forceinline__ float gelu_exact(float x) {
    return 0.5f * x * (1.0f + erff(x * 0.70710678118654752440f));
}
__device__ __forceinline__ uint32_t smem_to_u32(const void* p) {
    uint32_t a;
    asm("{ .reg .u64 t; cvta.to.shared.u64 t, %1; cvt.u32.u64 %0, t; }" : "=r"(a) : "l"(p));
    return a;
}
__device__ __forceinline__ void cp_async16(uint32_t dst, const void* src, int src_sz) {
    asm volatile("cp.async.cg.shared.global [%0], [%1], 16, %2;" :: "r"(dst), "l"(src), "r"(src_sz) : "memory");
}
__device__ __forceinline__ void cp_async_commit() { asm volatile("cp.async.commit_group;" ::: "memory"); }
template <int N> __device__ __forceinline__ void cp_async_wait() {
    asm volatile("cp.async.wait_group %0;" :: "n"(N) : "memory");
}
__device__ __forceinline__ void ldsm_x4(uint32_t& r0, uint32_t& r1, uint32_t& r2, uint32_t& r3, uint32_t addr) {
    asm volatile("ldmatrix.sync.aligned.m8n8.x4.shared.b16 {%0,%1,%2,%3}, [%4];"
                 : "=r"(r0), "=r"(r1), "=r"(r2), "=r"(r3) : "r"(addr));
}
__device__ __forceinline__ void mma16816(float* d, uint32_t a0, uint32_t a1, uint32_t a2, uint32_t a3,
                                         uint32_t b0, uint32_t b1) {
    asm volatile("mma.sync.aligned.m16n8k16.row.col.f32.f16.f16.f32 "
                 "{%0,%1,%2,%3}, {%4,%5,%6,%7}, {%8,%9}, {%0,%1,%2,%3};"
                 : "+f"(d[0]), "+f"(d[1]), "+f"(d[2]), "+f"(d[3])
                 : "r"(a0), "r"(a1), "r"(a2), "r"(a3), "r"(b0), "r"(b1));
}

// ---------------------------------------------------------------------------
// Prep: convert x -> fp16 mirror (4 elems/thread) and zero g_hist
// ---------------------------------------------------------------------------
__global__ void __launch_bounds__(256) prep_x_kernel(const float* __restrict__ x) {
    int gid = blockIdx.x * blockDim.x + threadIdx.x;
    if (gid < N_NODES * 64) {
        float4 v = ((const float4*)x)[gid];
        __half2 a = __halves2half2(__float2half(v.x), __float2half(v.y));
        __half2 b = __halves2half2(__float2half(v.z), __float2half(v.w));
        ((__half2*)g_xh)[gid * 2 + 0] = a;
        ((__half2*)g_xh)[gid * 2 + 1] = b;
    }
    if (gid < N_NODES) g_hist[gid] = 0;
}

// 8 edges per thread (N_EDGES % 8 == 0)
__global__ void __launch_bounds__(256) hist_kernel(const int* __restrict__ dst) {
    int g8 = (blockIdx.x * blockDim.x + threadIdx.x) * 8;
    if (g8 >= N_EDGES) return;
    int4 d0 = *(const int4*)(dst + g8);
    int4 d1 = *(const int4*)(dst + g8 + 4);
    atomicAdd(&g_hist[d0.x], 1);
    atomicAdd(&g_hist[d0.y], 1);
    atomicAdd(&g_hist[d0.z], 1);
    atomicAdd(&g_hist[d0.w], 1);
    atomicAdd(&g_hist[d1.x], 1);
    atomicAdd(&g_hist[d1.y], 1);
    atomicAdd(&g_hist[d1.z], 1);
    atomicAdd(&g_hist[d1.w], 1);
}

// single block 1024 threads, 20 bins each
__global__ void __launch_bounds__(1024) scan_kernel() {
    __shared__ int sm[1024];
    int t = threadIdx.x;
    int base = t * 20;
    int cnt[20];
    int s = 0;
#pragma unroll
    for (int i = 0; i < 20; i++) {
        int idx = base + i;
        int c = (idx < N_NODES) ? g_hist[idx] : 0;
        cnt[i] = c; s += c;
    }
    sm[t] = s;
    __syncthreads();
    for (int off = 1; off < 1024; off <<= 1) {
        int v = (t >= off) ? sm[t - off] : 0;
        __syncthreads();
        sm[t] += v;
        __syncthreads();
    }
    int run = (t > 0) ? sm[t - 1] : 0;
#pragma unroll
    for (int i = 0; i < 20; i++) {
        int idx = base + i;
        if (idx < N_NODES) {
            g_start[idx] = run;
            g_cursor[idx] = run;
            run += cnt[i];
        }
    }
    if (t == 1023) g_start[N_NODES] = sm[1023];
}

// 8 edges per thread
__global__ void __launch_bounds__(256) reorder_kernel(const int* __restrict__ src,
                                                      const int* __restrict__ dst,
                                                      const int* __restrict__ et) {
    int g8 = (blockIdx.x * blockDim.x + threadIdx.x) * 8;
    if (g8 >= N_EDGES) return;
    int4 s0 = *(const int4*)(src + g8);
    int4 s1 = *(const int4*)(src + g8 + 4);
    int4 d0 = *(const int4*)(dst + g8);
    int4 d1 = *(const int4*)(dst + g8 + 4);
    int4 t0 = *(const int4*)(et + g8);
    int4 t1 = *(const int4*)(et + g8 + 4);
    int p0 = atomicAdd(&g_cursor[d0.x], 1);
    int p1 = atomicAdd(&g_cursor[d0.y], 1);
    int p2 = atomicAdd(&g_cursor[d0.z], 1);
    int p3 = atomicAdd(&g_cursor[d0.w], 1);
    int p4 = atomicAdd(&g_cursor[d1.x], 1);
    int p5 = atomicAdd(&g_cursor[d1.y], 1);
    int p6 = atomicAdd(&g_cursor[d1.z], 1);
    int p7 = atomicAdd(&g_cursor[d1.w], 1);
    g_edges[p0] = (uint32_t)s0.x | ((uint32_t)t0.x << 15);
    g_edges[p1] = (uint32_t)s0.y | ((uint32_t)t0.y << 15);
    g_edges[p2] = (uint32_t)s0.z | ((uint32_t)t0.z << 15);
    g_edges[p3] = (uint32_t)s0.w | ((uint32_t)t0.w << 15);
    g_edges[p4] = (uint32_t)s1.x | ((uint32_t)t1.x << 15);
    g_edges[p5] = (uint32_t)s1.y | ((uint32_t)t1.y << 15);
    g_edges[p6] = (uint32_t)s1.z | ((uint32_t)t1.z << 15);
    g_edges[p7] = (uint32_t)s1.w | ((uint32_t)t1.w << 15);
}

// ---------------------------------------------------------------------------
// Prep B2 (K = 1280 fp16):
//   k<1024  : b=k>>8, i=k&255 -> fp16(basis[b][i][n])
//   k>=1024 : i=k&255         -> fp16(loop_w[i][n])
// ---------------------------------------------------------------------------
__global__ void __launch_bounds__(256) prep_b2_kernel(const float* __restrict__ basis,
                                                      const float* __restrict__ loopw) {
    int n = blockIdx.x;   // 0..255
    for (int k = threadIdx.x; k < KA; k += 256) {
        float w;
        if (k < 1024) {
            int b = k >> 8, i = k & 255;
            w = basis[(size_t)b * 65536 + (size_t)i * 256 + n];
        } else {
            int i = k & 255;
            w = loopw[(size_t)i * 256 + n];
        }
        g_B2[(size_t)n * KA + k] = __float2half(w);
    }
}

// ---------------------------------------------------------------------------
// Fused gather(fp16) + aggregate + combine: one warp per node.
// A row layout (KA=1280): [T_hi(1024)|x_hi(256)]
// ---------------------------------------------------------------------------
__device__ __forceinline__ void round8_store(__half* rowbase, int off, const float* v) {
    union { __half2 h2[4]; uint4 u; } p;
#pragma unroll
    for (int q = 0; q < 4; q++)
        p.h2[q] = __halves2half2(__float2half(v[q * 2]), __float2half(v[q * 2 + 1]));
    *(uint4*)(rowbase + off) = p.u;
}

__global__ void __launch_bounds__(256) agg_kernel(const float* __restrict__ comp) {
    __shared__ float4 cs4[N_RELS];
    int tid = threadIdx.x;
    if (tid < N_RELS)
        cs4[tid] = make_float4(comp[tid * 4 + 0], comp[tid * 4 + 1], comp[tid * 4 + 2], comp[tid * 4 + 3]);
    __syncthreads();

    int v = blockIdx.x * 8 + (tid >> 5);
    int lane = tid & 31;
    if (v >= N_NODES) return;

    int s0 = g_start[v];
    int s1 = g_start[v + 1];
    int c0 = lane * 8;

    float accT[4][8];
#pragma unroll
    for (int b = 0; b < 4; b++)
#pragma unroll
        for (int j = 0; j < 8; j++) accT[b][j] = 0.f;

    auto accum = [&](uint32_t p, uint4 xv) {
        float4 cv = cs4[p >> 15];
        const __half2* h2 = (const __half2*)&xv;
        float2 f0 = __half22float2(h2[0]);
        float2 f1 = __half22float2(h2[1]);
        float2 f2 = __half22float2(h2[2]);
        float2 f3 = __half22float2(h2[3]);
        float c;
        c = cv.x;
        accT[0][0] += c * f0.x; accT[0][1] += c * f0.y; accT[0][2] += c * f1.x; accT[0][3] += c * f1.y;
        accT[0][4] += c * f2.x; accT[0][5] += c * f2.y; accT[0][6] += c * f3.x; accT[0][7] += c * f3.y;
        c = cv.y;
        accT[1][0] += c * f0.x; accT[1][1] += c * f0.y; accT[1][2] += c * f1.x; accT[1][3] += c * f1.y;
        accT[1][4] += c * f2.x; accT[1][5] += c * f2.y; accT[1][6] += c * f3.x; accT[1][7] += c * f3.y;
        c = cv.z;
        accT[2][0] += c * f0.x; accT[2][1] += c * f0.y; accT[2][2] += c * f1.x; accT[2][3] += c * f1.y;
        accT[2][4] += c * f2.x; accT[2][5] += c * f2.y; accT[2][6] += c * f3.x; accT[2][7] += c * f3.y;
        c = cv.w;
        accT[3][0] += c * f0.x; accT[3][1] += c * f0.y; accT[3][2] += c * f1.x; accT[3][3] += c * f1.y;
        accT[3][4] += c * f2.x; accT[3][5] += c * f2.y; accT[3][6] += c * f3.x; accT[3][7] += c * f3.y;
    };

    int e = s0;
    for (; e + 4 <= s1; e += 4) {
        uint32_t p[4];
        uint4 xv[4];
#pragma unroll
        for (int j = 0; j < 4; j++) p[j] = __ldg(&g_edges[e + j]);
#pragma unroll
        for (int j = 0; j < 4; j++)
            xv[j] = *(const uint4*)(g_xh + (size_t)(p[j] & 32767) * 256 + c0);
#pragma unroll
        for (int j = 0; j < 4; j++) accum(p[j], xv[j]);
    }
    for (; e < s1; e++) {
        uint32_t p = __ldg(&g_edges[e]);
        uint4 xv = *(const uint4*)(g_xh + (size_t)(p & 32767) * 256 + c0);
        accum(p, xv);
    }

    __half* arow = g_A3 + (size_t)v * KA;
#pragma unroll
    for (int b = 0; b < 4; b++)
        round8_store(arow, b * 256 + c0, accT[b]);
    // x part: copy the already-quantized fp16 row
    *(uint4*)(arow + 1024 + c0) = *(const uint4*)(g_xh + (size_t)v * 256 + c0);
}

// ---------------------------------------------------------------------------
// Fused GEMM + GELU + LayerNorm (M=64 tiles, R13 mainloop):
//   rgcn[64,256] = A[m0:m0+64, 1280] @ B2^T ; h = gelu(rgcn + bias + x);
//   out = LN(h)*gamma + beta.
// 8 warps: warp_m = wid&1 (2 x 32 rows), warp_n = wid>>1 (4 x 64 cols).
// Epilogue: spill acc -> fp32 smem overlay [64][260], warp w does rows 8w..8w+7.
// ---------------------------------------------------------------------------
#define KCH 32
#define NCH (KA / KCH)          // 40
#define ROWB 80
#define A_TILE (64 * ROWB)      // 5120
#define B_TILE (256 * ROWB)     // 20480
#define MAINLOOP_SMEM (2 * A_TILE + 2 * B_TILE)   // 51200
#define SROW 260
#define EPI_SMEM (64 * SROW * 4)                  // 66560
#define GEMM_SMEM (EPI_SMEM > MAINLOOP_SMEM ? EPI_SMEM : MAINLOOP_SMEM)

__global__ void __launch_bounds__(256) gemm_fused_kernel(const float* __restrict__ x,
                                                         const float* __restrict__ bias,
                                                         const float* __restrict__ gamma,
                                                         const float* __restrict__ beta,
                                                         float* __restrict__ out) {
    extern __shared__ __align__(16) char dyn[];
    const uint32_t sAu[2] = { smem_to_u32(dyn), smem_to_u32(dyn + A_TILE) };
    const uint32_t sBu[2] = { smem_to_u32(dyn + 2 * A_TILE), smem_to_u32(dyn + 2 * A_TILE + B_TILE) };
    float* sC = (float*)dyn;   // epilogue overlay

    const int tid = threadIdx.x;
    const int lane = tid & 31;
    const int wid = tid >> 5;
    const int warp_m = wid & 1;
    const int warp_n = wid >> 1;
    const int m0 = blockIdx.x * 64;

    const int ar = tid >> 2;
    const int ac = tid & 3;
    const int am = m0 + ar;
    const int asz = (am < N_NODES) ? 16 : 0;
    const __half* aBase = g_A3 + (size_t)((am < N_NODES) ? am : 0) * KA + ac * 8;
    const uint32_t aDst = ar * ROWB + ac * 16;

    auto load_chunk = [&](int c, int s) {
        int k0 = c * KCH;
        cp_async16(sAu[s] + aDst, aBase + k0, asz);
#pragma unroll
        for (int i = 0; i < 4; i++) {
            int cid = tid + i * 256;
            int br = cid >> 2, bc = cid & 3;
            cp_async16(sBu[s] + br * ROWB + bc * 16,
                       g_B2 + (size_t)br * KA + k0 + bc * 8, 16);
        }
        cp_async_commit();
    };

    float acc[2][8][4];
#pragma unroll
    for (int i = 0; i < 2; i++)
#pragma unroll
        for (int t = 0; t < 8; t++)
#pragma unroll
            for (int q = 0; q < 4; q++) acc[i][t][q] = 0.0f;

    const uint32_t aLd = (warp_m * 32 + (lane & 15)) * ROWB + (lane >> 4) * 16;
    const uint32_t bLd = (warp_n * 64 + ((lane >> 4) << 3) + (lane & 7)) * ROWB + (((lane >> 3) & 1) << 4);

    load_chunk(0, 0);
    for (int c = 0; c < NCH; c++) {
        if (c + 1 < NCH) load_chunk(c + 1, (c + 1) & 1);
        if (c + 1 < NCH) cp_async_wait<1>(); else cp_async_wait<0>();
        __syncthreads();
        const int s = c & 1;
#pragma unroll
        for (int kk = 0; kk < 2; kk++) {
            uint32_t a[2][4];
#pragma unroll
            for (int i = 0; i < 2; i++)
                ldsm_x4(a[i][0], a[i][1], a[i][2], a[i][3],
                        sAu[s] + aLd + i * 16 * ROWB + kk * 32);
            uint32_t b[4][4];
#pragma unroll
            for (int j = 0; j < 4; j++)
                ldsm_x4(b[j][0], b[j][1], b[j][2], b[j][3],
                        sBu[s] + bLd + j * 16 * ROWB + kk * 32);
#pragma unroll
            for (int i = 0; i < 2; i++)
#pragma unroll
                for (int t = 0; t < 8; t++)
                    mma16816(acc[i][t], a[i][0], a[i][1], a[i][2], a[i][3],
                             b[t >> 1][(t & 1) * 2], b[t >> 1][(t & 1) * 2 + 1]);
        }
        __syncthreads();
    }

    // ---- epilogue phase 1: spill acc -> smem fp32 [64][SROW]
    const int colBase = warp_n * 64 + (lane & 3) * 2;
#pragma unroll
    for (int i = 0; i < 2; i++) {
        int r0 = warp_m * 32 + i * 16 + (lane >> 2);
#pragma unroll
        for (int half = 0; half < 2; half++) {
            int r = r0 + half * 8;
#pragma unroll
            for (int t = 0; t < 8; t++)
                *(float2*)(sC + r * SROW + colBase + t * 8) =
                    make_float2(acc[i][t][half * 2], acc[i][t][half * 2 + 1]);
        }
    }
    __syncthreads();

    // ---- epilogue phase 2: warp w handles rows 8w..8w+7; GELU + LN
#pragma unroll
    for (int rr = 0; rr < 8; rr++) {
        int r = wid * 8 + rr;
        int m = m0 + r;
        if (m >= N_NODES) break;
        int c0 = lane * 8;

        float h[8];
        {
            const float* srow = sC + r * SROW + c0;
            const float4* xr = (const float4*)(x + (size_t)m * 256 + c0);
            const float4* br = (const float4*)(bias + c0);
            float4 x0 = __ldg(xr), x1 = __ldg(xr + 1);
            float4 b0 = __ldg(br), b1 = __ldg(br + 1);
            h[0] = gelu_exact(srow[0] + b0.x + x0.x);
            h[1] = gelu_exact(srow[1] + b0.y + x0.y);
            h[2] = gelu_exact(srow[2] + b0.z + x0.z);
            h[3] = gelu_exact(srow[3] + b0.w + x0.w);
            h[4] = gelu_exact(srow[4] + b1.x + x1.x);
            h[5] = gelu_exact(srow[5] + b1.y + x1.y);
            h[6] = gelu_exact(srow[6] + b1.z + x1.z);
            h[7] = gelu_exact(srow[7] + b1.w + x1.w);
        }

        float s = 0.f;
#pragma unroll
        for (int i = 0; i < 8; i++) s += h[i];
#pragma unroll
        for (int off = 16; off > 0; off >>= 1) s += __shfl_xor_sync(0xffffffffu, s, off);
        float mu = s * (1.0f / 256.0f);

        float var = 0.f;
#pragma unroll
        for (int i = 0; i < 8; i++) {
            float dlt = h[i] - mu;
            var = fmaf(dlt, dlt, var);
        }
#pragma unroll
        for (int off = 16; off > 0; off >>= 1) var += __shfl_xor_sync(0xffffffffu, var, off);
        float inv = rsqrtf(var * (1.0f / 256.0f) + 1e-5f);

        float4 g0 = __ldg((const float4*)(gamma + c0));
        float4 g1 = __ldg((const float4*)(gamma + c0) + 1);
        float4 be0 = __ldg((const float4*)(beta + c0));
        float4 be1 = __ldg((const float4*)(beta + c0) + 1);

        float4 o0, o1;
        o0.x = (h[0] - mu) * inv * g0.x + be0.x;
        o0.y = (h[1] - mu) * inv * g0.y + be0.y;
        o0.z = (h[2] - mu) * inv * g0.z + be0.z;
        o0.w = (h[3] - mu) * inv * g0.w + be0.w;
        o1.x = (h[4] - mu) * inv * g1.x + be1.x;
        o1.y = (h[5] - mu) * inv * g1.y + be1.y;
        o1.z = (h[6] - mu) * inv * g1.z + be1.z;
        o1.w = (h[7] - mu) * inv * g1.w + be1.w;

        float4* orow = (float4*)(out + (size_t)m * 256 + c0);
        orow[0] = o0;
        orow[1] = o1;
    }
}

extern "C" void kernel_launch(void* const* d_in, const int* in_sizes, int n_in,
                              void* d_out, int out_size) {
    const float* x     = (const float*)d_in[0];
    const int*   src   = (const int*)  d_in[1];
    const int*   dst   = (const int*)  d_in[2];
    const int*   et    = (const int*)  d_in[3];
    const float* basis = (const float*)d_in[4];
    const float* comp  = (const float*)d_in[5];
    const float* loopw = (const float*)d_in[6];
    const float* bias  = (const float*)d_in[7];
    const float* gamma = (const float*)d_in[8];
    const float* beta  = (const float*)d_in[9];
    float* out = (float*)d_out;

    static bool attr_set = false;
    if (!attr_set) {
        cudaFuncSetAttribute(gemm_fused_kernel, cudaFuncAttributeMaxDynamicSharedMemorySize, GEMM_SMEM);
        attr_set = true;
    }

    prep_x_kernel<<<(N_NODES * 64 + 255) / 256, 256>>>(x);
    hist_kernel<<<(N_EDGES / 8 + 255) / 256, 256>>>(dst);
    scan_kernel<<<1, 1024>>>();
    reorder_kernel<<<(N_EDGES / 8 + 255) / 256, 256>>>(src, dst, et);
    prep_b2_kernel<<<256, 256>>>(basis, loopw);
    agg_kernel<<<(N_NODES + 7) / 8, 256>>>(comp);
    gemm_fused_kernel<<<(N_NODES + 63) / 64, 256, GEMM_SMEM>>>(x, bias, gamma, beta, out);
}